// round 11
// baseline (speedup 1.0000x reference)
#include <cuda_runtime.h>
#include <cuda_fp16.h>
#include <cstdint>

#define BATCH 4096
#define INDIM 2048
#define HID   2048
#define KTOT  4096

#define BM 128
#define BN 128
#define BK 64
#define NSTG (KTOT / BK)                 // 64 k-chunks

#define ROWB 144                         // 128B data + 16B pad per row
#define TILE_BYTES (128 * ROWB)          // 18432
#define OFF_A 0
#define OFF_B TILE_BYTES
#define STAGE_BYTES (2 * TILE_BYTES)     // 36864
#define NPIPE 3
#define SMEM_BYTES (NPIPE * STAGE_BYTES) // 110592 (2 CTAs = 221KB <= 228KB/SM)

#define DELTA    2e-3f
#define LIST_CAP (1u << 21)

// ---------------- device scratch ----------------
__device__ __half g_Ah[(size_t)BATCH * KTOT];    // [m][k]: fp16(X) | fp16(S)
__device__ __half g_Bh[(size_t)HID * KTOT];      // [n][k]: Wpsp^T | Wrec^T fp16
__device__ float  g_WfT[(size_t)HID * KTOT];     // [n][k]: exact fp32 W^T concat
__device__ uint32_t g_count;
__device__ uint32_t g_list[LIST_CAP];

// ---------------- helpers ----------------
__device__ __forceinline__ uint32_t s2u(const void* p) {
    uint32_t a;
    asm("{ .reg .u64 t; cvta.to.shared.u64 t, %1; cvt.u32.u64 %0, t; }"
        : "=r"(a) : "l"(p));
    return a;
}
__device__ __forceinline__ void cp16(uint32_t d, const void* s) {
    asm volatile("cp.async.cg.shared.global [%0], [%1], 16;" :: "r"(d), "l"(s));
}
__device__ __forceinline__ void ldm4(uint32_t* r, uint32_t addr) {
    asm volatile("ldmatrix.sync.aligned.m8n8.x4.shared.b16 {%0,%1,%2,%3}, [%4];"
                 : "=r"(r[0]), "=r"(r[1]), "=r"(r[2]), "=r"(r[3]) : "r"(addr));
}
__device__ __forceinline__ void mma16(float* d, const uint32_t* a, const uint32_t* b) {
    asm volatile(
        "mma.sync.aligned.m16n8k16.row.col.f32.f16.f16.f32 "
        "{%0,%1,%2,%3},{%4,%5,%6,%7},{%8,%9},{%0,%1,%2,%3};"
        : "+f"(d[0]), "+f"(d[1]), "+f"(d[2]), "+f"(d[3])
        : "r"(a[0]), "r"(a[1]), "r"(a[2]), "r"(a[3]), "r"(b[0]), "r"(b[1]));
}

// ---------------- pre-kernels ----------------
__global__ void build_a_k(const float* __restrict__ X, const float* __restrict__ S) {
    size_t i = (size_t)blockIdx.x * blockDim.x + threadIdx.x;   // half2 index
    if (i == 0) g_count = 0;
    const size_t n2 = (size_t)BATCH * KTOT / 2;
    if (i >= n2) return;
    const int m = (int)(i >> 11);
    const int k = (int)(i & 2047) * 2;
    float2 v;
    if (k < INDIM) v = *(const float2*)(X + (size_t)m * INDIM + k);
    else           v = *(const float2*)(S + (size_t)m * HID + (k - INDIM));
    ((__half2*)g_Ah)[i] = __floats2half2_rn(v.x, v.y);
}
__global__ void trans_w_k(const float* __restrict__ Wpsp,
                          const float* __restrict__ Wrec) {
    __shared__ float tile[32][33];
    const float* W = blockIdx.z ? Wrec : Wpsp;
    const int off = blockIdx.z ? INDIM : 0;
    const int n0 = blockIdx.x * 32, k0 = blockIdx.y * 32;
    const int tx = threadIdx.x, ty = threadIdx.y;
    #pragma unroll
    for (int r = ty; r < 32; r += 8)
        tile[r][tx] = W[(size_t)(k0 + r) * HID + n0 + tx];
    __syncthreads();
    #pragma unroll
    for (int r = ty; r < 32; r += 8) {
        float v = tile[tx][r];                    // = W[k0+tx][n0+r]
        size_t o = (size_t)(n0 + r) * KTOT + off + k0 + tx;
        g_Bh[o]  = __float2half_rn(v);
        g_WfT[o] = v;
    }
}

// ---------------- main fused GEMM + LIF + band detect ----------------
__global__ void __launch_bounds__(256, 2)
gemm_lif(const float* __restrict__ S, const float* __restrict__ preC,
         const float* __restrict__ preV, const float* __restrict__ preTh,
         const float* __restrict__ mask, const float* __restrict__ bpsp,
         const float* __restrict__ brec, float* __restrict__ out, int sections)
{
    extern __shared__ char smem[];
    const uint32_t sb = s2u(smem);
    const int tid = threadIdx.x;
    const int lane = tid & 31, warp = tid >> 5;
    const int g = lane >> 2, t4 = lane & 3;
    const int wm = warp >> 2, wn = warp & 3;            // 2 x 4 warps, 64x32 tiles
    const int m0 = blockIdx.y * BM, n0 = blockIdx.x * BN;

    const uint32_t aoff = (uint32_t)((lane & 15) * ROWB + (lane >> 4) * 16);
    const uint32_t boff =
        (uint32_t)((((lane & 7) + ((lane >> 4) & 1) * 8)) * ROWB + ((lane >> 3) & 1) * 16);

    float acc[4][4][4];
    #pragma unroll
    for (int i = 0; i < 4; i++)
        #pragma unroll
        for (int j = 0; j < 4; j++)
            #pragma unroll
            for (int q = 0; q < 4; q++) acc[i][j][q] = 0.0f;

    // loader: A = 4 chunks, B = 4 chunks of 16B per thread (8 chunks/row)
    auto load_stage = [&](int t) {
        const uint32_t base = sb + (uint32_t)((t % NPIPE) * STAGE_BYTES);
        const int k0 = t * BK;
        #pragma unroll
        for (int i = 0; i < 4; i++) {
            const int u = tid + i * 256;
            const int r = u >> 3, c = u & 7;
            const uint32_t d = (uint32_t)(r * ROWB + c * 16);
            cp16(base + OFF_A + d, g_Ah + (size_t)(m0 + r) * KTOT + k0 + c * 8);
            cp16(base + OFF_B + d, g_Bh + (size_t)(n0 + r) * KTOT + k0 + c * 8);
        }
    };

    uint32_t fa[4][4], fb[4][2];
    auto compute_half = [&](uint32_t stb, int h) {
        const uint32_t kb = (uint32_t)(h * 32);              // k16 = 32 bytes
        #pragma unroll
        for (int mf = 0; mf < 4; mf++)
            ldm4(fa[mf], stb + OFF_A + (uint32_t)((wm * 64 + mf * 16) * ROWB) + kb + aoff);
        #pragma unroll
        for (int p = 0; p < 2; p++) {
            uint32_t r[4];
            ldm4(r, stb + OFF_B + (uint32_t)((wn * 32 + p * 16) * ROWB) + kb + boff);
            fb[2 * p][0] = r[0]; fb[2 * p][1] = r[1];
            fb[2 * p + 1][0] = r[2]; fb[2 * p + 1][1] = r[3];
        }
        #pragma unroll
        for (int mf = 0; mf < 4; mf++)
            #pragma unroll
            for (int nf = 0; nf < 4; nf++)
                mma16(acc[mf][nf], fa[mf], fb[nf]);
    };

    load_stage(0);
    asm volatile("cp.async.commit_group;" ::: "memory");
    load_stage(1);
    asm volatile("cp.async.commit_group;" ::: "memory");

    for (int t = 0; t < NSTG; ++t) {
        if (t + 1 < NSTG)
            asm volatile("cp.async.wait_group 1;" ::: "memory");
        else
            asm volatile("cp.async.wait_group 0;" ::: "memory");
        __syncthreads();
        if (t + 2 < NSTG) {
            load_stage(t + 2);
            asm volatile("cp.async.commit_group;" ::: "memory");
        }

        const uint32_t stb = sb + (uint32_t)((t % NPIPE) * STAGE_BYTES);
        compute_half(stb, 0);
        compute_half(stb, 1);
        compute_half(stb, 2);
        compute_half(stb, 3);
    }

    // ---------------- fused LIF epilogue + warp-aggregated band detect ----------------
    const size_t NE = (size_t)BATCH * HID;
    #pragma unroll
    for (int mf = 0; mf < 4; mf++) {
        #pragma unroll
        for (int rh = 0; rh < 2; rh++) {
            const int m = m0 + wm * 64 + mf * 16 + g + rh * 8;
            const size_t row = (size_t)m * HID;
            #pragma unroll
            for (int nf = 0; nf < 4; nf++) {
                const int n = n0 + wn * 32 + nf * 8 + 2 * t4;
                const size_t idx = row + n;
                float2 pc = *(const float2*)(preC  + idx);
                float2 pv = *(const float2*)(preV  + idx);
                float2 ps = *(const float2*)(S     + idx);
                float2 pt = *(const float2*)(preTh + idx);
                float2 mk = *(const float2*)(mask  + idx);
                float2 b1 = *(const float2*)(bpsp  + n);
                float2 b2 = *(const float2*)(brec  + n);

                float av[2]  = { acc[mf][nf][rh * 2 + 0], acc[mf][nf][rh * 2 + 1] };
                float pcv[2] = { pc.x, pc.y }, pvv[2] = { pv.x, pv.y };
                float psv[2] = { ps.x, ps.y }, ptv[2] = { pt.x, pt.y };
                float mkv[2] = { mk.x, mk.y };
                float b1v[2] = { b1.x, b1.y }, b2v[2] = { b2.x, b2.y };

                float sp[2], cu[2], vo[2], th[2];
                #pragma unroll
                for (int q = 0; q < 2; q++) {
                    float c = fmaf(0.5f, pcv[q], av[q] + b1v[q] + b2v[q]);
                    c *= mkv[q];
                    float v = fmaf(0.75f * pvv[q], (1.0f - psv[q]), c);
                    float s = (v > ptv[q]) ? 1.0f : 0.0f;
                    float tv = (s != 0.0f) ? (ptv[q] + 0.05f)
                                           : fmaxf(ptv[q] * 0.9f, 1.0f);
                    sp[q] = s; cu[q] = c; vo[q] = v; th[q] = tv;

                    const bool f = fabsf(v - ptv[q]) < DELTA;
                    const unsigned bal = __ballot_sync(0xFFFFFFFFu, f);
                    if (bal) {
                        const int leader = __ffs(bal) - 1;
                        uint32_t base = 0;
                        if (lane == leader)
                            base = atomicAdd(&g_count, (uint32_t)__popc(bal));
                        base = __shfl_sync(0xFFFFFFFFu, base, leader);
                        if (f) {
                            uint32_t pos = base + __popc(bal & ((1u << lane) - 1));
                            if (pos < LIST_CAP)
                                g_list[pos] = (uint32_t)((m << 11) | (n + q));
                        }
                    }
                }
                *(float2*)(out + idx) = make_float2(sp[0], sp[1]);
                if (sections > 1) *(float2*)(out + NE + idx)     = make_float2(sp[0], sp[1]);
                if (sections > 2) *(float2*)(out + 2 * NE + idx) = make_float2(cu[0], cu[1]);
                if (sections > 3) *(float2*)(out + 3 * NE + idx) = make_float2(vo[0], vo[1]);
                if (sections > 4) *(float2*)(out + 4 * NE + idx) = make_float2(th[0], th[1]);
            }
        }
    }
}

// ---------------- exact fp32 fixup (vectorized float4 loads) ----------------
__global__ void fixup_k(const float* __restrict__ X, const float* __restrict__ S,
                        const float* __restrict__ preC, const float* __restrict__ preV,
                        const float* __restrict__ preTh, const float* __restrict__ mask,
                        const float* __restrict__ bpsp, const float* __restrict__ brec,
                        float* __restrict__ out, int sections)
{
    const int lane = threadIdx.x & 31;
    const uint32_t wglob = (blockIdx.x * blockDim.x + threadIdx.x) >> 5;
    const uint32_t nw = (gridDim.x * blockDim.x) >> 5;
    uint32_t cnt = g_count;
    if (cnt > LIST_CAP) cnt = LIST_CAP;
    const size_t NE = (size_t)BATCH * HID;

    for (uint32_t i = wglob; i < cnt; i += nw) {
        const uint32_t e = g_list[i];
        const int m = (int)(e >> 11), n = (int)(e & 2047);
        const float4* xr = (const float4*)(X + (size_t)m * INDIM);
        const float4* sr = (const float4*)(S + (size_t)m * HID);
        const float4* wr = (const float4*)(g_WfT + (size_t)n * KTOT);
        const float4* rr = (const float4*)(g_WfT + (size_t)n * KTOT + INDIM);
        float a = 0.0f;
        #pragma unroll 4
        for (int k = lane; k < INDIM / 4; k += 32) {
            float4 x = xr[k], w = wr[k];
            a = fmaf(x.x, w.x, a); a = fmaf(x.y, w.y, a);
            a = fmaf(x.z, w.z, a); a = fmaf(x.w, w.w, a);
        }
        #pragma unroll 4
        for (int k = lane; k < HID / 4; k += 32) {
            float4 x = sr[k], w = rr[k];
            a = fmaf(x.x, w.x, a); a = fmaf(x.y, w.y, a);
            a = fmaf(x.z, w.z, a); a = fmaf(x.w, w.w, a);
        }
        #pragma unroll
        for (int o = 16; o; o >>= 1) a += __shfl_xor_sync(0xFFFFFFFFu, a, o);

        if (lane == 0) {
            const size_t idx = (size_t)m * HID + n;
            float c = fmaf(0.5f, preC[idx], a + bpsp[n] + brec[n]);
            c *= mask[idx];
            float v = fmaf(0.75f * preV[idx], (1.0f - S[idx]), c);
            float pt = preTh[idx];
            float sp = (v > pt) ? 1.0f : 0.0f;
            float tv = (sp != 0.0f) ? (pt + 0.05f) : fmaxf(pt * 0.9f, 1.0f);
            out[idx] = sp;
            if (sections > 1) out[NE + idx]     = sp;
            if (sections > 2) out[2 * NE + idx] = c;
            if (sections > 3) out[3 * NE + idx] = v;
            if (sections > 4) out[4 * NE + idx] = tv;
        }
    }
}

// ---------------- launch ----------------
extern "C" void kernel_launch(void* const* d_in, const int* in_sizes, int n_in,
                              void* d_out, int out_size) {
    const float* X     = (const float*)d_in[0];
    const float* S     = (const float*)d_in[1];
    const float* preC  = (const float*)d_in[2];
    const float* preV  = (const float*)d_in[3];
    const float* preTh = (const float*)d_in[4];
    const float* mk    = (const float*)d_in[5];
    const float* Wpsp  = (const float*)d_in[6];
    const float* bpsp  = (const float*)d_in[7];
    const float* Wrec  = (const float*)d_in[8];
    const float* brec  = (const float*)d_in[9];

    const long long NE = (long long)BATCH * HID;
    int sections = (int)((long long)out_size / NE);
    if (sections < 1) sections = 1;
    if (sections > 5) sections = 5;

    cudaFuncSetAttribute(gemm_lif, cudaFuncAttributeMaxDynamicSharedMemorySize,
                         SMEM_BYTES);

    const size_t n2 = (size_t)BATCH * KTOT / 2;
    build_a_k<<<(unsigned)((n2 + 255) / 256), 256>>>(X, S);
    dim3 wg(HID / 32, KTOT / 2 / 32, 2), wb(32, 8);
    trans_w_k<<<wg, wb>>>(Wpsp, Wrec);

    dim3 grid(HID / BN, BATCH / BM);   // (16, 32) = 512 CTAs
    gemm_lif<<<grid, 256, SMEM_BYTES>>>(S, preC, preV, preTh, mk, bpsp, brec,
                                        (float*)d_out, sections);
    fixup_k<<<1024, 256>>>(X, S, preC, preV, preTh, mk, bpsp, brec,
                           (float*)d_out, sections);
}